// round 17
// baseline (speedup 1.0000x reference)
#include <cuda_runtime.h>
#include <cuda_fp16.h>
#include <float.h>
#include <math.h>

#define CCH 128
#define HWF 409600   // 640*640
#define WF 640
#define HF 640
#define NTPB (HWF / 64)   // 6400 transpose blocks (64 pixels each)
#define NMAX 20000
#define PPB 48            // points per matvec block

// Slot permutation: slot s holds channel c(s) = (s&3)*32 + (s>>2); s(o) = 4*(o&31)+(o>>5)
__device__ __align__(16) __half d_Msp[CCH * CCH];   // Msp[s_in*128+s_out]
__device__ __align__(16) float  d_up[CCH];
__device__ __align__(16) __half d_f1t[(size_t)HWF * CCH];   // [pixel][slot]
__device__ __align__(16) float  d_r0[NMAX * CCH];           // [n][slot]
__device__ __align__(16) float  d_g[NMAX * CCH];            // [n][slot]
__device__ int d_cnt  = 0;   // release-counter: precompute + gather blocks
__device__ int d_done = 0;   // matvec completion counter (for self-reset)

// packed fp32x2 FMA (Blackwell)
#define FMA_F32X2(d, a, b, c) \
    asm("fma.rn.f32x2 %0, %1, %2, %3;" : "=l"(d) : "l"(a), "l"(b), "l"(c))

__device__ __forceinline__ unsigned long long pack_f32x2(float lo, float hi) {
    unsigned long long r;
    unsigned ulo = __float_as_uint(lo), uhi = __float_as_uint(hi);
    asm("mov.b64 %0, {%1, %2};" : "=l"(r) : "r"(ulo), "r"(uhi));
    return r;
}
__device__ __forceinline__ void unpack_f32x2(unsigned long long v, float& lo, float& hi) {
    unsigned ulo, uhi;
    asm("mov.b64 {%0, %1}, %2;" : "=r"(ulo), "=r"(uhi) : "l"(v));
    lo = __uint_as_float(ulo);
    hi = __uint_as_float(uhi);
}

// ---------------------------------------------------------------------------
// Kernel 1 "prep_fused": four roles by block index.
//   blk < 128                      : precompute Msp/up  (increments d_cnt)
//   128 <= blk < 128+grps*7        : r=blk-128, sub=r%7:
//       sub<5  -> transpose tile grp*5+sub
//       sub>=5 -> gather 8 points  (increments d_cnt, even if idle)
//   blk >= 128+grps*7              : matvec block midx (spins on d_cnt)
// Dynamic smem 43584 B used only by matvec role (<48KB, 5 blocks/SM).
#define R0PITCH 20
#define MV_SMEM 43584
__global__ void __launch_bounds__(256)
prep_fused(const float* __restrict__ f1,
           const float* __restrict__ W, const float* __restrict__ b,
           const float* __restrict__ mk0, const float* __restrict__ f0,
           const int* __restrict__ stride_ptr, int N,
           int grps, int target, int nMatvec)
{
    extern __shared__ char smraw[];
    __shared__ float wcol[CCH];
    const int blk = blockIdx.x;
    const int t = threadIdx.x;
    const int w = t >> 5, l = t & 31;

    if (blk < 128) {
        // ---- precompute role: row o of M = W^T W, slot-permuted ----
        const int o = blk;
        if (t < CCH) wcol[t] = W[t * CCH + o];
        __syncthreads();
        if (t < CCH) {
            float acc = 0.f;
#pragma unroll 8
            for (int k = 0; k < CCH; k++) acc += wcol[k] * W[k * CCH + t];
            const int so = 4 * (o & 31) + (o >> 5);
            const int st = 4 * (t & 31) + (t >> 5);
            d_Msp[so * CCH + st] = __float2half(acc);   // symmetric
            if (t == 0) {
                float uu = 0.f;
                for (int k = 0; k < CCH; k++) uu += wcol[k] * b[k];
                d_up[so] = uu;
            }
        }
        __syncthreads();
        if (t == 0) { __threadfence(); atomicAdd(&d_cnt, 1); }
        return;
    }

    if (blk < 128 + grps * 7) {
        const int r = blk - 128;
        const int grp = r / 7, sub = r % 7;

        if (sub < 5) {
            // ---- transpose role: 64 pixels; lane = 2 pixels, warp = 16 slots ----
            const int tidx = grp * 5 + sub;
            if (tidx >= NTPB) return;
            const int p0 = tidx * 64 + 2 * l;
            float2 v[16];
#pragma unroll
            for (int d = 0; d < 16; d++) {
                const int c = 4 * w + (d >> 2) + 32 * (d & 3);
                v[d] = __ldg((const float2*)(f1 + (size_t)c * HWF + p0));
            }
#pragma unroll
            for (int j2 = 0; j2 < 2; j2++) {
                unsigned q[8];
#pragma unroll
                for (int d = 0; d < 8; d++) {
                    const float a  = j2 ? v[2 * d].y     : v[2 * d].x;
                    const float bq = j2 ? v[2 * d + 1].y : v[2 * d + 1].x;
                    __half2 h = __floats2half2_rn(a, bq);
                    q[d] = *reinterpret_cast<unsigned*>(&h);
                }
                __half* dst = d_f1t + (size_t)(p0 + j2) * CCH + 16 * w;
                *reinterpret_cast<uint4*>(dst)     = make_uint4(q[0], q[1], q[2], q[3]);
                *reinterpret_cast<uint4*>(dst + 8) = make_uint4(q[4], q[5], q[6], q[7]);
            }
            return;
        }

        // ---- gather role: 8 points (one per warp), lane loads 4 channels ----
        {
            const int gidx = grp * 2 + (sub - 5);
            const int n = gidx * 8 + w;
            if (n < N) {
                const int stride = stride_ptr ? __ldg(stride_ptr) : 8;
                const int fr = stride >> 1;
                const float m0x = __ldg(&mk0[2 * n]), m0y = __ldg(&mk0[2 * n + 1]);
                const int cx0 = (int)(m0x * (float)fr), cy0 = (int)(m0y * (float)fr);
                const int cx0c = min(max(cx0, 2), WF - 3), cy0c = min(max(cy0, 2), HF - 3);
                const int pix0 = cy0c * WF + cx0c;
                float v0 = __ldg(f0 + (size_t)(l      ) * HWF + pix0);
                float v1 = __ldg(f0 + (size_t)(l + 32 ) * HWF + pix0);
                float v2 = __ldg(f0 + (size_t)(l + 64 ) * HWF + pix0);
                float v3 = __ldg(f0 + (size_t)(l + 96 ) * HWF + pix0);
                *(float4*)&d_r0[(size_t)n * CCH + 4 * l] = make_float4(v0, v1, v2, v3);
            }
            __syncthreads();
            if (t == 0) { __threadfence(); atomicAdd(&d_cnt, 1); }
            return;
        }
    }

    // ---- matvec role: wait for Msp + r0, then g = Msp*r0 + up (48 pts) ----
    {
        const int midx = blk - (128 + grps * 7);
        if (midx >= nMatvec) return;

        if (t == 0) {
            while (atomicAdd(&d_cnt, 0) < target) __nanosleep(128);
            __threadfence();   // acquire
        }
        __syncthreads();

        __half* Msh = (__half*)smraw;                  // 32768 B
        float*  r0p = (float*)(smraw + 32768);         // 128*20*4 = 10240 B
        float*  ush = (float*)(smraw + 43008);         // 512 B

        {   // stage fp16 Msp (uint4) and up
            const uint4* Ms = (const uint4*)d_Msp;
            uint4* Md = (uint4*)Msh;
#pragma unroll
            for (int i = 0; i < 8; i++) Md[i * 256 + t] = __ldg(&Ms[i * 256 + t]);
            if (t < CCH) ush[t] = d_up[t];
        }

        const int o    = t & 127;
        const int half = t >> 7;
        const int n0blk = midx * PPB;

#pragma unroll
        for (int bb = 0; bb < 3; bb++) {
            // load r0 batch (coalesced from dense d_r0)
#pragma unroll
            for (int k = 0; k < 8; k++) {
                const int q = half * 8 + k;
                const int nc = min(n0blk + bb * 16 + q, N - 1);
                r0p[o * R0PITCH + q] = __ldg(&d_r0[(size_t)nc * CCH + o]);
            }
            __syncthreads();   // also covers Msh staging before first use

            const float uo = ush[o];
            unsigned long long a0 = pack_f32x2(uo, uo);
            unsigned long long a1 = a0, a2 = a0, a3 = a0;
            const int qb = half * 8;
#pragma unroll 8
            for (int c = 0; c < CCH; c++) {
                const float m = __half2float(Msh[c * CCH + o]);
                const unsigned long long m2 = pack_f32x2(m, m);
                const unsigned long long* rp =
                    (const unsigned long long*)&r0p[c * R0PITCH + qb];
                FMA_F32X2(a0, m2, rp[0], a0);
                FMA_F32X2(a1, m2, rp[1], a1);
                FMA_F32X2(a2, m2, rp[2], a2);
                FMA_F32X2(a3, m2, rp[3], a3);
            }
            float g[8];
            unpack_f32x2(a0, g[0], g[1]);
            unpack_f32x2(a1, g[2], g[3]);
            unpack_f32x2(a2, g[4], g[5]);
            unpack_f32x2(a3, g[6], g[7]);
#pragma unroll
            for (int k = 0; k < 8; k++) {
                const int n = n0blk + bb * 16 + qb + k;
                if (n < N) d_g[(size_t)n * CCH + o] = g[k];
            }
            __syncthreads();   // r0p reads done before next batch overwrite
        }

        // self-reset for next launch/replay: last matvec block zeroes counters
        if (t == 0) {
            const int v = atomicAdd(&d_done, 1);
            if (v == nMatvec - 1) {
                d_cnt = 0;
                d_done = 0;
                __threadfence();
            }
        }
    }
}

// ---------------------------------------------------------------------------
// Kernel 2: one warp per point: correlation (fp16 f1t) + softmax + outputs.
__global__ void __launch_bounds__(256)
corr_kernel(const float* __restrict__ mk0, const float* __restrict__ mk1,
            const int* __restrict__ stride_ptr, float* __restrict__ out, int N)
{
    const int wid = threadIdx.x >> 5, lane = threadIdx.x & 31;
    const int n = blockIdx.x * 8 + wid;
    if (n >= N) return;

    const int stride = stride_ptr ? __ldg(stride_ptr) : 8;
    const int fr = stride >> 1;
    const float scalef = (float)(stride / fr);
    const float halfstr = (float)(stride >> 1);

    const float m0x = __ldg(&mk0[2 * n]), m0y = __ldg(&mk0[2 * n + 1]);
    const float m1x = __ldg(&mk1[2 * n]), m1y = __ldg(&mk1[2 * n + 1]);
    const int cx0 = (int)(m0x * (float)fr), cy0 = (int)(m0y * (float)fr);
    const int cx1 = (int)(m1x * (float)fr), cy1 = (int)(m1y * (float)fr);
    const bool valid = cx0 >= 2 && cx0 + 2 < WF && cy0 >= 2 && cy0 + 2 < HF &&
                       cx1 >= 2 && cx1 + 2 < WF && cy1 >= 2 && cy1 + 2 < HF;
    const int cx1c = min(max(cx1, 2), WF - 3);
    const int cy1c = min(max(cy1, 2), HF - 3);
    const size_t pixb = (size_t)cy1c * WF + cx1c;

    // slots 4*lane..4*lane+3
    const float4 g4 = *(const float4*)&d_g[(size_t)n * CCH + lane * 4];

    float corr = -FLT_MAX;   // lane p (p<25) ends up holding corr[p]
#pragma unroll
    for (int row = 0; row < 5; row++) {
        const size_t rb = (pixb + (size_t)(row - 2) * WF - 2) * CCH + lane * 4;
        float r[5];
#pragma unroll
        for (int col = 0; col < 5; col++) {
            uint2 u = __ldg((const uint2*)(d_f1t + rb + (size_t)col * CCH));
            __half2 h0 = *reinterpret_cast<__half2*>(&u.x);
            __half2 h1 = *reinterpret_cast<__half2*>(&u.y);
            float2 f01 = __half22float2(h0);
            float2 f23 = __half22float2(h1);
            r[col] = g4.x * f01.x + g4.y * f01.y + g4.z * f23.x + g4.w * f23.y;
        }
#pragma unroll
        for (int d = 16; d; d >>= 1) {
            r[0] += __shfl_xor_sync(0xffffffffu, r[0], d);
            r[1] += __shfl_xor_sync(0xffffffffu, r[1], d);
            r[2] += __shfl_xor_sync(0xffffffffu, r[2], d);
            r[3] += __shfl_xor_sync(0xffffffffu, r[3], d);
            r[4] += __shfl_xor_sync(0xffffffffu, r[4], d);
        }
        const int p0 = row * 5;
#pragma unroll
        for (int col = 0; col < 5; col++)
            if (lane == p0 + col) corr = r[col];
    }

    // softmax over lanes 0..24 + expectation (per-point constant cancels)
    const bool inpatch = lane < 25;
    const int dx = lane % 5 - 2;
    const int dy = lane / 5 - 2;
    float cm = corr;
#pragma unroll
    for (int d = 16; d; d >>= 1)
        cm = fmaxf(cm, __shfl_xor_sync(0xffffffffu, cm, d));
    float e  = inpatch ? __expf(corr - cm) : 0.f;
    float ex = e * (float)dx;
    float ey = e * (float)dy;
    float s  = e;
#pragma unroll
    for (int d = 16; d; d >>= 1) {
        s  += __shfl_xor_sync(0xffffffffu, s,  d);
        ex += __shfl_xor_sync(0xffffffffu, ex, d);
        ey += __shfl_xor_sync(0xffffffffu, ey, d);
    }
    if (lane == 0) {
        out[2 * n]     = m0x * (float)stride + halfstr;
        out[2 * n + 1] = m0y * (float)stride + halfstr;
        const float inv = scalef / s;
        const float ox = valid ? ex * inv : 0.f;
        const float oy = valid ? ey * inv : 0.f;
        out[2 * N + 2 * n]     = m1x * (float)stride + halfstr + ox;
        out[2 * N + 2 * n + 1] = m1y * (float)stride + halfstr + oy;
    }
}

// ---------------------------------------------------------------------------
extern "C" void kernel_launch(void* const* d_in, const int* in_sizes, int n_in,
                              void* d_out, int out_size) {
    const float* mk0 = (const float*)d_in[0];
    const float* mk1 = (const float*)d_in[1];
    const float* f0  = (const float*)d_in[2];
    const float* f1  = (const float*)d_in[3];
    const float* pw  = (const float*)d_in[4];
    const float* pb  = (const float*)d_in[5];
    const int* stridep = (n_in >= 7) ? (const int*)d_in[6] : nullptr;
    float* out = (float*)d_out;

    int N = in_sizes[0] / 2;

    int ngather = (N + 15) / 16;           // useful gather blocks (2 per group)
    int grpsT = (NTPB + 4) / 5;            // 1280
    int grpsG = (ngather + 1) / 2;
    int grps = grpsT > grpsG ? grpsT : grpsG;
    int nMatvec = (N + PPB - 1) / PPB;     // 417
    int target = 128 + grps * 2;           // every gather-role block increments

    int grid = 128 + grps * 7 + nMatvec;
    prep_fused<<<grid, 256, MV_SMEM>>>(f1, pw, pb, mk0, f0, stridep, N,
                                       grps, target, nMatvec);

    corr_kernel<<<(N + 7) / 8, 256>>>(mk0, mk1, stridep, out, N);
}